// round 5
// baseline (speedup 1.0000x reference)
#include <cuda_runtime.h>
#include <math.h>
#include <stdint.h>

#define B_  4
#define T_  32
#define C_  128
#define HW_ 1024
#define N_  4096
#define GD_ 64
#define M_  (T_*N_)      // 131072 rows, r = t*N_ + n
#define F_  512

// ---------------- scratch (device globals; no allocation) ----------------
static __device__ float g_mu[M_];
static __device__ float g_rs[M_];
static __device__ float g_q [(size_t)M_*C_];
static __device__ float g_k [(size_t)M_*C_];
static __device__ float g_v [(size_t)M_*C_];
static __device__ float g_at[(size_t)M_*C_];

// ---------------- helpers -------------------------------------------------
#define CP4(dst, src) asm volatile("cp.async.ca.shared.global [%0], [%1], 4;" \
                                   :: "r"(dst), "l"(src) : "memory")
#define CPCOMMIT()    asm volatile("cp.async.commit_group;" ::: "memory")
#define CPWAIT(n)     asm volatile("cp.async.wait_group %0;" :: "n"(n) : "memory")

__device__ __forceinline__ float rna(float f){
    float r; asm("cvt.rna.tf32.f32 %0, %1;" : "=f"(r) : "f"(f)); return r;
}
__device__ __forceinline__ void mma8(float* d, const uint32_t* a,
                                     uint32_t b0, uint32_t b1){
    asm volatile(
        "mma.sync.aligned.m16n8k8.row.col.f32.tf32.tf32.f32 "
        "{%0,%1,%2,%3}, {%4,%5,%6,%7}, {%8,%9}, {%0,%1,%2,%3};"
        : "+f"(d[0]), "+f"(d[1]), "+f"(d[2]), "+f"(d[3])
        : "r"(a[0]), "r"(a[1]), "r"(a[2]), "r"(a[3]), "r"(b0), "r"(b1));
}
// interleaved k position: within each 8-group store order [0,4,1,5,2,6,3,7]
__device__ __forceinline__ int kperm(int k){
    return ((k >> 3) << 3) + ((k & 3) << 1) + ((k & 7) >> 2);
}
// cp.async fill of a weight half-tile into interleaved n-major layout
// dst[n*stridef + kperm(klocal)] = W[(kbeg+klocal)*ldw + col0 + n]
__device__ __forceinline__ void fill_w(uint32_t sbase, int stridef,
                                       const float* __restrict__ W, size_t ldw,
                                       int kbeg, int kcnt, int col0, int tid)
{
    const int n = tid & 127, half = tid >> 7;
    const uint32_t rb = sbase + (uint32_t)(n * stridef) * 4u;
    const float* src = W + (size_t)kbeg * ldw + col0 + n;
    for (int p = 0; p < kcnt/2; p++){
        int k = half + 2*p;
        CP4(rb + (uint32_t)kperm(k) * 4u, src + (size_t)k * ldw);
    }
}
// MMA over kstep range [ks0,ks1): warp tile 32x64, A rows wm*32.., B cols wn*64..
__device__ __forceinline__ void mma_block(
    float acc[][8][4], const float* __restrict__ sA, int strA,
    const float* __restrict__ sW, int strW,
    int ks0, int ks1, int kloc0, int wm, int wn, int gid, int tig)
{
    #pragma unroll 2
    for (int ks = ks0; ks < ks1; ks++){
        const int ka = ks*8 + tig*2;
        const int kw = (ks - kloc0)*8 + tig*2;
        float2 f0 = *(const float2*)&sA[(wm*32 +      gid)*strA + ka];
        float2 f1 = *(const float2*)&sA[(wm*32 +  8 + gid)*strA + ka];
        float2 f2 = *(const float2*)&sA[(wm*32 + 16 + gid)*strA + ka];
        float2 f3 = *(const float2*)&sA[(wm*32 + 24 + gid)*strA + ka];
        uint32_t a0[4] = {__float_as_uint(f0.x), __float_as_uint(f1.x),
                          __float_as_uint(f0.y), __float_as_uint(f1.y)};
        uint32_t a1[4] = {__float_as_uint(f2.x), __float_as_uint(f3.x),
                          __float_as_uint(f2.y), __float_as_uint(f3.y)};
        #pragma unroll
        for (int j = 0; j < 8; j++){
            float2 bb = *(const float2*)&sW[(wn*64 + j*8 + gid)*strW + kw];
            uint32_t b0 = __float_as_uint(bb.x), b1 = __float_as_uint(bb.y);
            mma8(acc[0][j], a0, b0, b1);
            mma8(acc[1][j], a1, b0, b1);
        }
    }
}

// ---------------- kernel 1: merged QKV GEMM + ln1 stats ------------------
// 256 thr, 8 warps (4m x 2n), CTA tile 128 rows x 128 cols.
// smem floats: sA[128*200] | sWa[128*104] | sWb[128*104]
__global__ __launch_bounds__(256) void k_qkv_tc(
    const float* __restrict__ x, const float* __restrict__ gdn,
    const float* __restrict__ Wq, const float* __restrict__ bq,
    const float* __restrict__ Wk, const float* __restrict__ bk,
    const float* __restrict__ Wv, const float* __restrict__ bv)
{
    extern __shared__ float sm[];
    float* sA  = sm;
    float* sWa = sm + 25600;
    float* sWb = sm + 38912;
    const uint32_t sAu  = (uint32_t)__cvta_generic_to_shared(sA);
    const uint32_t sWau = (uint32_t)__cvta_generic_to_shared(sWa);
    const uint32_t sWbu = (uint32_t)__cvta_generic_to_shared(sWb);

    const int tid = threadIdx.x;
    const int lane = tid & 31, wid = tid >> 5;
    const int wm = wid >> 1, wn = wid & 1;
    const int gid = lane >> 2, tig = lane & 3;

    const int r0 = blockIdx.x * 128;
    const int t  = r0 / N_,  n0 = r0 % N_;
    const int b  = n0 / HW_, hw0 = n0 % HW_;
    const float* xbt = x   + (size_t)(b*T_ + t) * C_ * HW_;
    const float* gbt = gdn + (size_t)(b*T_ + t) * GD_;

    // fill A (x-transpose || guidance), interleaved, via cp.async
    {
        const int rl = tid & 127, half = tid >> 7;
        const uint32_t rb = sAu + (uint32_t)(rl * 200) * 4u;
        for (int p = 0; p < 96; p++){
            int c = half + 2*p;
            const float* src = (c < C_) ? (xbt + (size_t)c*HW_ + hw0 + rl)
                                        : (gbt + (c - C_));
            CP4(rb + (uint32_t)kperm(c) * 4u, src);
        }
    }
    CPCOMMIT();                                        // G0
    fill_w(sWau, 104, Wq, C_, 0,  96, 0, tid); CPCOMMIT();  // G1
    fill_w(sWbu, 104, Wq, C_, 96, 96, 0, tid); CPCOMMIT();  // G2
    CPWAIT(2); __syncthreads();                        // G0,G1 done

    // ln1 stats from exact x in sA (positions 0..127 = channels, permuted)
    if (tid < 128){
        float s = 0.f, s2 = 0.f;
        for (int i = 0; i < 128; i++){ float v = sA[tid*200 + i]; s += v; s2 += v*v; }
        float mu = s * (1.0f/C_);
        g_mu[r0+tid] = mu;
        g_rs[r0+tid] = rsqrtf(s2 * (1.0f/C_) - mu*mu + 1e-5f);
    }

    float acc[2][8][4];
    #define ZACC() { _Pragma("unroll") for(int m2=0;m2<2;m2++) \
                     _Pragma("unroll") for(int j2=0;j2<8;j2++) \
                     _Pragma("unroll") for(int q2=0;q2<4;q2++) acc[m2][j2][q2]=0.f; }
    #define EPI(OUTP, BS, Y) { \
        _Pragma("unroll") for (int mb = 0; mb < 2; mb++){ \
            const int ra = wm*32 + mb*16 + gid; \
            _Pragma("unroll") for (int j = 0; j < 8; j++){ \
                const int col = wn*64 + j*8 + 2*tig; \
                float bb0 = BS[col], bb1 = BS[col+1]; \
                float v0 = acc[mb][j][0]+bb0, v1 = acc[mb][j][1]+bb1; \
                float v2 = acc[mb][j][2]+bb0, v3 = acc[mb][j][3]+bb1; \
                if (Y < 2){ \
                    v0 = v0>0.f ? v0+1.f : expf(v0); v1 = v1>0.f ? v1+1.f : expf(v1); \
                    v2 = v2>0.f ? v2+1.f : expf(v2); v3 = v3>0.f ? v3+1.f : expf(v3); \
                } else { v0*=(1.f/T_); v1*=(1.f/T_); v2*=(1.f/T_); v3*=(1.f/T_); } \
                *(float2*)&OUTP[(size_t)(r0+ra)*C_ + col]   = make_float2(v0,v1); \
                *(float2*)&OUTP[(size_t)(r0+ra+8)*C_ + col] = make_float2(v2,v3); \
            } } }

    // ---- Q ----
    ZACC();
    mma_block(acc, sA,200, sWa,104, 0,12,0, wm,wn,gid,tig);
    __syncthreads(); fill_w(sWau,104, Wk, C_, 0, 96, 0, tid); CPCOMMIT();   // G3
    CPWAIT(1); __syncthreads();                        // G2 done
    mma_block(acc, sA,200, sWb,104, 12,24,12, wm,wn,gid,tig);
    EPI(g_q, bq, 0);
    __syncthreads(); fill_w(sWbu,104, Wk, C_, 96, 96, 0, tid); CPCOMMIT();  // G4
    CPWAIT(1); __syncthreads();                        // G3 done
    // ---- K ----
    ZACC();
    mma_block(acc, sA,200, sWa,104, 0,12,0, wm,wn,gid,tig);
    __syncthreads(); fill_w(sWau,104, Wv, C_, 0, 96, 0, tid); CPCOMMIT();   // G5
    CPWAIT(1); __syncthreads();                        // G4 done
    mma_block(acc, sA,200, sWb,104, 12,24,12, wm,wn,gid,tig);
    EPI(g_k, bk, 1);
    __syncthreads(); fill_w(sWbu,104, Wv, C_, 96, 32, 0, tid); CPCOMMIT();  // G6
    CPWAIT(1); __syncthreads();                        // G5 done
    // ---- V ----
    ZACC();
    mma_block(acc, sA,200, sWa,104, 0,12,0, wm,wn,gid,tig);
    CPWAIT(0); __syncthreads();                        // G6 done
    mma_block(acc, sA,200, sWb,104, 12,16,12, wm,wn,gid,tig);
    EPI(g_v, bv, 2);
    #undef ZACC
    #undef EPI
}

// ---------------- kernel 2: linear attention (unchanged) -----------------
__global__ __launch_bounds__(128) void k_attn()
{
    __shared__ __align__(16) float pool[4224*2 + 256];
    float* pK    = pool;
    float* pV    = pool + 4224;
    float* sKsum = pool + 8448;
    float* sZ    = pool + 8448 + 128;
    const int n = blockIdx.x;
    const int tid = threadIdx.x;

    for (int s = 0; s < 32; s++) {
        pK[s*132 + tid] = g_k[(size_t)(s*N_ + n)*C_ + tid];
        pV[s*132 + tid] = g_v[(size_t)(s*N_ + n)*C_ + tid];
    }
    __syncthreads();

    const int h = tid >> 5, d = tid & 31;
    float kv[32];
    #pragma unroll
    for (int vv = 0; vv < 32; vv++) kv[vv] = 0.f;
    float ks = 0.f;
    for (int s = 0; s < 32; s++) {
        float kd = pK[s*132 + h*32 + d];
        ks += kd;
        const float* vrow = &pV[s*132 + h*32];
        #pragma unroll
        for (int vv = 0; vv < 32; vv += 4) {
            float4 vf = *(const float4*)&vrow[vv];
            kv[vv+0] += kd * vf.x;
            kv[vv+1] += kd * vf.y;
            kv[vv+2] += kd * vf.z;
            kv[vv+3] += kd * vf.w;
        }
    }
    __syncthreads();
    #pragma unroll
    for (int vv = 0; vv < 32; vv++)
        pV[h*1056 + d*33 + vv] = kv[vv];
    sKsum[tid] = ks;
    for (int s = 0; s < 32; s++)
        pK[s*132 + tid] = g_q[(size_t)(s*N_ + n)*C_ + tid];
    __syncthreads();
    {
        int tz = tid >> 2, hz = tid & 3;
        float z = 0.f;
        #pragma unroll
        for (int dd = 0; dd < 32; dd++)
            z += pK[tz*132 + hz*32 + dd] * sKsum[hz*32 + dd];
        sZ[tz*4 + hz] = (float)T_ / (z + 1e-6f);
    }
    __syncthreads();
    const float* kvb = &pV[h*1056];
    for (int tt = 0; tt < 32; tt++) {
        float acc = 0.f;
        const float* qrow = &pK[tt*132 + h*32];
        #pragma unroll
        for (int dd = 0; dd < 32; dd++)
            acc += qrow[dd] * kvb[dd*33 + d];
        g_at[(size_t)(tt*N_ + n)*C_ + tid] = acc * sZ[tt*4 + h];
    }
}

// ---------------- kernel 3: FFN, pipelined cp.async + mma.sync -----------
// 256 thr, 8 warps (4m x 2n), CTA tile 128 rows.
// smem floats: sOH[128*136] | sU[128*136] | sWa[128*72] | sWb[128*72] | sM2 | sR2
__global__ __launch_bounds__(256) void k_ffn_tc(
    const float* __restrict__ x,
    const float* __restrict__ l1g, const float* __restrict__ l1b,
    const float* __restrict__ l2g, const float* __restrict__ l2b,
    const float* __restrict__ W1,  const float* __restrict__ b1f,
    const float* __restrict__ W2,  const float* __restrict__ b2f,
    float* __restrict__ out)
{
    extern __shared__ float sm[];
    float* sOH = sm;
    float* sU  = sm + 17408;
    float* sWa = sm + 34816;
    float* sWb = sm + 44032;
    float* sM2 = sm + 53248;
    float* sR2 = sm + 53376;
    const uint32_t sWau = (uint32_t)__cvta_generic_to_shared(sWa);
    const uint32_t sWbu = (uint32_t)__cvta_generic_to_shared(sWb);

    const int tid = threadIdx.x;
    const int lane = tid & 31, wid = tid >> 5;
    const int wm = wid >> 1, wn = wid & 1;
    const int gid = lane >> 2, tig = lane & 3;

    const int r0 = blockIdx.x * 128;
    const int t  = r0 / N_,  n0 = r0 % N_;
    const int b  = n0 / HW_, hw0 = n0 % HW_;

    // pre-issue W1(jc=0) halves so they land during the prologue
    fill_w(sWau, 72, W1, F_, 0,  64, 0, tid); CPCOMMIT();
    fill_w(sWbu, 72, W1, F_, 64, 64, 0, tid); CPCOMMIT();

    // ---- prologue: sOH = attn + ln1(x) (pad 136) ----
    {
        const int cc = (tid & 31) * 4;
        const int rb = tid >> 5;               // 0..7
        for (int j = 0; j < 16; j++) {
            int row = rb + 8*j;
            float4 a = *(const float4*)&g_at[(size_t)(r0+row)*C_ + cc];
            *(float4*)&sOH[row*136 + cc] = a;
        }
    }
    __syncthreads();
    {
        const int rl = tid & 127, cq = tid >> 7;
        const float mu = g_mu[r0+rl], rs = g_rs[r0+rl];
        const float* xb = x + (size_t)(b*T_+t)*C_*HW_ + hw0 + rl;
        for (int c = cq; c < C_; c += 2)
            sOH[rl*136 + c] += (xb[(size_t)c*HW_] - mu)*rs*l1g[c] + l1b[c];
    }
    __syncthreads();
    if (tid < 128) {   // ln2 stats
        float s = 0.f, s2 = 0.f;
        for (int c = 0; c < C_; c++) { float v = sOH[tid*136+c]; s += v; s2 += v*v; }
        float mu = s*(1.f/C_);
        sM2[tid] = mu;
        sR2[tid] = rsqrtf(s2*(1.f/C_) - mu*mu + 1e-5f);
    }
    __syncthreads();
    {   // sU = tf32(ln2(O)), interleaved, float2 stores
        const int rl = tid >> 1, cq = tid & 1;
        const float mu = sM2[rl], rs = sR2[rl];
        for (int q = 0; q < 16; q++)
            #pragma unroll
            for (int i = 0; i < 2; i++){
                int kb = 2*cq + i;
                int c  = q*8 + kb;
                float f0 = (sOH[rl*136 + c  ] - mu)*rs*l2g[c  ] + l2b[c  ];
                float f4 = (sOH[rl*136 + c+4] - mu)*rs*l2g[c+4] + l2b[c+4];
                *(float2*)&sU[rl*136 + q*8 + kb*2] = make_float2(rna(f0), rna(f4));
            }
    }
    // acc2 = O + b2 (residual + final bias pre-loaded; reads sOH before gelu reuse)
    float acc2[2][8][4];
    #pragma unroll
    for (int mb = 0; mb < 2; mb++){
        const int ra = wm*32 + mb*16 + gid;
        #pragma unroll
        for (int j = 0; j < 8; j++){
            const int col = wn*64 + j*8 + 2*tig;
            acc2[mb][j][0] = sOH[ra*136 + col]       + b2f[col];
            acc2[mb][j][1] = sOH[ra*136 + col + 1]   + b2f[col+1];
            acc2[mb][j][2] = sOH[(ra+8)*136 + col]   + b2f[col];
            acc2[mb][j][3] = sOH[(ra+8)*136 + col+1] + b2f[col+1];
        }
    }
    __syncthreads();   // sU ready; all acc2-init reads of sOH done

    float acc1[2][8][4];
    for (int jc = 0; jc < 4; jc++) {
        CPWAIT(1); __syncthreads();            // W1 lo ready
        #pragma unroll
        for (int mb = 0; mb < 2; mb++)
            #pragma unroll
            for (int j = 0; j < 8; j++){
                const int col = jc*128 + wn*64 + j*8 + 2*tig;
                acc1[mb][j][0] = b1f[col];   acc1[mb][j][1] = b1f[col+1];
                acc1[mb][j][2] = b1f[col];   acc1[mb][j][3] = b1f[col+1];
            }
        mma_block(acc1, sU,136, sWa,72, 0,8,0, wm,wn,gid,tig);
        __syncthreads(); fill_w(sWau, 72, W2, C_, jc*128,     64, 0, tid); CPCOMMIT();
        CPWAIT(1); __syncthreads();            // W1 hi ready
        mma_block(acc1, sU,136, sWb,72, 8,16,8, wm,wn,gid,tig);
        // gelu -> sOH (interleaved layout for GEMM2 A-operand)
        #pragma unroll
        for (int mb = 0; mb < 2; mb++){
            const int ra = wm*32 + mb*16 + gid;
            #pragma unroll
            for (int j = 0; j < 8; j++){
                const int c0 = wn*64 + j*8 + 2*tig, c1 = c0 + 1;
                float g0 = acc1[mb][j][0], g1 = acc1[mb][j][1];
                float g2 = acc1[mb][j][2], g3 = acc1[mb][j][3];
                g0 = rna(0.5f*g0*(1.f + erff(g0*0.70710678118f)));
                g1 = rna(0.5f*g1*(1.f + erff(g1*0.70710678118f)));
                g2 = rna(0.5f*g2*(1.f + erff(g2*0.70710678118f)));
                g3 = rna(0.5f*g3*(1.f + erff(g3*0.70710678118f)));
                sOH[ra*136     + kperm(c0)] = g0;
                sOH[ra*136     + kperm(c1)] = g1;
                sOH[(ra+8)*136 + kperm(c0)] = g2;
                sOH[(ra+8)*136 + kperm(c1)] = g3;
            }
        }
        __syncthreads(); fill_w(sWbu, 72, W2, C_, jc*128+64,  64, 0, tid); CPCOMMIT();
        CPWAIT(1); __syncthreads();            // W2 lo ready
        mma_block(acc2, sOH,136, sWa,72, 0,8,0, wm,wn,gid,tig);
        __syncthreads();
        if (jc < 3){ fill_w(sWau, 72, W1, F_, 0,  64, (jc+1)*128, tid); CPCOMMIT(); }
        if (jc < 3){ CPWAIT(1); } else { CPWAIT(0); }
        __syncthreads();                       // W2 hi ready
        mma_block(acc2, sOH,136, sWb,72, 8,16,8, wm,wn,gid,tig);
        __syncthreads();
        if (jc < 3){ fill_w(sWbu, 72, W1, F_, 64, 64, (jc+1)*128, tid); CPCOMMIT(); }
    }

    // ---- epilogue: direct transposed writeback (32B-sector aligned) ----
    {
        float* obase = out + (size_t)(b*T_+t)*C_*HW_ + hw0;
        #pragma unroll
        for (int mb = 0; mb < 2; mb++){
            const int ra = wm*32 + mb*16 + gid;
            #pragma unroll
            for (int j = 0; j < 8; j++){
                const int c0 = wn*64 + j*8 + 2*tig, c1 = c0 + 1;
                obase[(size_t)c0*HW_ + ra]     = acc2[mb][j][0];
                obase[(size_t)c1*HW_ + ra]     = acc2[mb][j][1];
                obase[(size_t)c0*HW_ + ra + 8] = acc2[mb][j][2];
                obase[(size_t)c1*HW_ + ra + 8] = acc2[mb][j][3];
            }
        }
    }
}

// ---------------- launch --------------------------------------------------
extern "C" void kernel_launch(void* const* d_in, const int* in_sizes, int n_in,
                              void* d_out, int out_size)
{
    (void)in_sizes; (void)n_in; (void)out_size;
    const float* x   = (const float*)d_in[0];
    const float* gd  = (const float*)d_in[1];
    const float* Wq  = (const float*)d_in[2];
    const float* bq  = (const float*)d_in[3];
    const float* Wk  = (const float*)d_in[4];
    const float* bk  = (const float*)d_in[5];
    const float* Wv  = (const float*)d_in[6];
    const float* bv  = (const float*)d_in[7];
    const float* l1g = (const float*)d_in[8];
    const float* l1b = (const float*)d_in[9];
    const float* l2g = (const float*)d_in[10];
    const float* l2b = (const float*)d_in[11];
    const float* W1  = (const float*)d_in[12];
    const float* b1  = (const float*)d_in[13];
    const float* W2  = (const float*)d_in[14];
    const float* b2  = (const float*)d_in[15];
    float* out = (float*)d_out;

    const int smemQkv = (25600 + 2*13312) * 4;            // 208,896 B
    const int smemFfn = (17408*2 + 9216*2 + 256) * 4;     // 214,016 B
    cudaFuncSetAttribute(k_qkv_tc, cudaFuncAttributeMaxDynamicSharedMemorySize, smemQkv);
    cudaFuncSetAttribute(k_ffn_tc, cudaFuncAttributeMaxDynamicSharedMemorySize, smemFfn);

    k_qkv_tc<<<M_/128, 256, smemQkv>>>(x, gd, Wq, bq, Wk, bk, Wv, bv);
    k_attn  <<<N_, 128>>>();
    k_ffn_tc<<<M_/128, 256, smemFfn>>>(x, l1g, l1b, l2g, l2b, W1, b1, W2, b2, out);
}

// round 6
// speedup vs baseline: 1.1093x; 1.1093x over previous
#include <cuda_runtime.h>
#include <math.h>
#include <stdint.h>

#define B_  4
#define T_  32
#define C_  128
#define HW_ 1024
#define N_  4096
#define GD_ 64
#define M_  (T_*N_)      // 131072 rows, r = t*N_ + n
#define F_  512

// ---------------- scratch (device globals; no allocation) ----------------
static __device__ float g_mu[M_];
static __device__ float g_rs[M_];
static __device__ float g_q [(size_t)M_*C_];
static __device__ float g_k [(size_t)M_*C_];
static __device__ float g_v [(size_t)M_*C_];
static __device__ float g_at[(size_t)M_*C_];

// ---------------- helpers -------------------------------------------------
#define CP4(dst, src) asm volatile("cp.async.ca.shared.global [%0], [%1], 4;" \
                                   :: "r"(dst), "l"(src) : "memory")
#define CPCOMMIT()    asm volatile("cp.async.commit_group;" ::: "memory")
#define CPWAIT(n)     asm volatile("cp.async.wait_group %0;" :: "n"(n) : "memory")

__device__ __forceinline__ float rna(float f){
    float r; asm("cvt.rna.tf32.f32 %0, %1;" : "=f"(r) : "f"(f)); return r;
}
__device__ __forceinline__ void mma8(float* d, const uint32_t* a,
                                     uint32_t b0, uint32_t b1){
    asm volatile(
        "mma.sync.aligned.m16n8k8.row.col.f32.tf32.tf32.f32 "
        "{%0,%1,%2,%3}, {%4,%5,%6,%7}, {%8,%9}, {%0,%1,%2,%3};"
        : "+f"(d[0]), "+f"(d[1]), "+f"(d[2]), "+f"(d[3])
        : "r"(a[0]), "r"(a[1]), "r"(a[2]), "r"(a[3]), "r"(b0), "r"(b1));
}
// interleaved k position: within each 8-group store order [0,4,1,5,2,6,3,7]
__device__ __forceinline__ int kperm(int k){
    return ((k >> 3) << 3) + ((k & 3) << 1) + ((k & 7) >> 2);
}
// cp.async fill (512 threads): dst[n*stridef + kperm(k)] = W[(kbeg+k)*ldw + col0 + n]
__device__ __forceinline__ void fill_w(uint32_t sbase, int stridef,
                                       const float* __restrict__ W, size_t ldw,
                                       int kbeg, int kcnt, int col0, int tid)
{
    const int n = tid & 127, q4 = tid >> 7;          // q4 in 0..3
    const uint32_t rb = sbase + (uint32_t)(n * stridef) * 4u;
    const float* src = W + (size_t)kbeg * ldw + col0 + n;
    for (int p = 0; p < kcnt/4; p++){
        int k = q4 + 4*p;
        CP4(rb + (uint32_t)kperm(k) * 4u, src + (size_t)k * ldw);
    }
}
// MMA over kstep range [ks0,ks1): warp tile 16x64 (16 warps: 8m x 2n)
__device__ __forceinline__ void mma_blk(
    float acc[][4], const float* __restrict__ sA, int strA,
    const float* __restrict__ sW, int strW,
    int ks0, int ks1, int kloc0, int wm, int wn, int gid, int tig)
{
    #pragma unroll 2
    for (int ks = ks0; ks < ks1; ks++){
        const int ka = ks*8 + tig*2;
        const int kw = (ks - kloc0)*8 + tig*2;
        float2 f0 = *(const float2*)&sA[(wm*16 +     gid)*strA + ka];
        float2 f1 = *(const float2*)&sA[(wm*16 + 8 + gid)*strA + ka];
        uint32_t a[4] = {__float_as_uint(f0.x), __float_as_uint(f1.x),
                         __float_as_uint(f0.y), __float_as_uint(f1.y)};
        #pragma unroll
        for (int j = 0; j < 8; j++){
            float2 bb = *(const float2*)&sW[(wn*64 + j*8 + gid)*strW + kw];
            mma8(acc[j], a, __float_as_uint(bb.x), __float_as_uint(bb.y));
        }
    }
}

// ---------------- kernel 1: merged QKV GEMM + ln1 stats ------------------
// 512 thr, 16 warps (8m x 2n), CTA tile 128 rows x 128 cols.
// smem floats: sA[128*200] | sWa[128*104] | sWb[128*104]
__global__ __launch_bounds__(512) void k_qkv_tc(
    const float* __restrict__ x, const float* __restrict__ gdn,
    const float* __restrict__ Wq, const float* __restrict__ bq,
    const float* __restrict__ Wk, const float* __restrict__ bk,
    const float* __restrict__ Wv, const float* __restrict__ bv)
{
    extern __shared__ float sm[];
    float* sA  = sm;
    float* sWa = sm + 25600;
    float* sWb = sm + 38912;
    const uint32_t sAu  = (uint32_t)__cvta_generic_to_shared(sA);
    const uint32_t sWau = (uint32_t)__cvta_generic_to_shared(sWa);
    const uint32_t sWbu = (uint32_t)__cvta_generic_to_shared(sWb);

    const int tid = threadIdx.x;
    const int lane = tid & 31, wid = tid >> 5;
    const int wm = wid >> 1, wn = wid & 1;
    const int gid = lane >> 2, tig = lane & 3;

    const int r0 = blockIdx.x * 128;
    const int t  = r0 / N_,  n0 = r0 % N_;
    const int b  = n0 / HW_, hw0 = n0 % HW_;
    const float* xbt = x   + (size_t)(b*T_ + t) * C_ * HW_;
    const float* gbt = gdn + (size_t)(b*T_ + t) * GD_;

    // fill A (x-transpose || guidance), interleaved, via cp.async
    {
        const int rl = tid & 127, q4 = tid >> 7;
        const uint32_t rb = sAu + (uint32_t)(rl * 200) * 4u;
        for (int p = 0; p < 48; p++){
            int c = q4 + 4*p;
            const float* src = (c < C_) ? (xbt + (size_t)c*HW_ + hw0 + rl)
                                        : (gbt + (c - C_));
            CP4(rb + (uint32_t)kperm(c) * 4u, src);
        }
    }
    CPCOMMIT();                                        // G0
    fill_w(sWau, 104, Wq, C_, 0,  96, 0, tid); CPCOMMIT();  // G1
    fill_w(sWbu, 104, Wq, C_, 96, 96, 0, tid); CPCOMMIT();  // G2
    CPWAIT(2); __syncthreads();                        // G0,G1 done

    // ln1 stats (positions 0..127 of each A row are a permutation of channels)
    if (tid < 128){
        float s = 0.f, s2 = 0.f;
        for (int i = 0; i < 128; i++){ float v = sA[tid*200 + i]; s += v; s2 += v*v; }
        float mu = s * (1.0f/C_);
        g_mu[r0+tid] = mu;
        g_rs[r0+tid] = rsqrtf(s2 * (1.0f/C_) - mu*mu + 1e-5f);
    }

    float acc[8][4];
    #define ZACC() { _Pragma("unroll") for(int j2=0;j2<8;j2++) \
                     _Pragma("unroll") for(int q2=0;q2<4;q2++) acc[j2][q2]=0.f; }
    #define EPI(OUTP, BS, Y) { \
        const int ra = wm*16 + gid; \
        _Pragma("unroll") for (int j = 0; j < 8; j++){ \
            const int col = wn*64 + j*8 + 2*tig; \
            float bb0 = BS[col], bb1 = BS[col+1]; \
            float v0 = acc[j][0]+bb0, v1 = acc[j][1]+bb1; \
            float v2 = acc[j][2]+bb0, v3 = acc[j][3]+bb1; \
            if (Y < 2){ \
                v0 = v0>0.f ? v0+1.f : expf(v0); v1 = v1>0.f ? v1+1.f : expf(v1); \
                v2 = v2>0.f ? v2+1.f : expf(v2); v3 = v3>0.f ? v3+1.f : expf(v3); \
            } else { v0*=(1.f/T_); v1*=(1.f/T_); v2*=(1.f/T_); v3*=(1.f/T_); } \
            *(float2*)&OUTP[(size_t)(r0+ra)*C_ + col]   = make_float2(v0,v1); \
            *(float2*)&OUTP[(size_t)(r0+ra+8)*C_ + col] = make_float2(v2,v3); \
        } }

    // ---- Q ----
    ZACC();
    mma_blk(acc, sA,200, sWa,104, 0,12,0, wm,wn,gid,tig);
    __syncthreads(); fill_w(sWau,104, Wk, C_, 0, 96, 0, tid); CPCOMMIT();   // G3
    CPWAIT(1); __syncthreads();                        // G2 done
    mma_blk(acc, sA,200, sWb,104, 12,24,12, wm,wn,gid,tig);
    EPI(g_q, bq, 0);
    __syncthreads(); fill_w(sWbu,104, Wk, C_, 96, 96, 0, tid); CPCOMMIT();  // G4
    CPWAIT(1); __syncthreads();                        // G3 done
    // ---- K ----
    ZACC();
    mma_blk(acc, sA,200, sWa,104, 0,12,0, wm,wn,gid,tig);
    __syncthreads(); fill_w(sWau,104, Wv, C_, 0, 96, 0, tid); CPCOMMIT();   // G5
    CPWAIT(1); __syncthreads();                        // G4 done
    mma_blk(acc, sA,200, sWb,104, 12,24,12, wm,wn,gid,tig);
    EPI(g_k, bk, 1);
    __syncthreads(); fill_w(sWbu,104, Wv, C_, 96, 32, 0, tid); CPCOMMIT();  // G6
    CPWAIT(1); __syncthreads();                        // G5 done
    // ---- V ----
    ZACC();
    mma_blk(acc, sA,200, sWa,104, 0,12,0, wm,wn,gid,tig);
    CPWAIT(0); __syncthreads();                        // G6 done
    mma_blk(acc, sA,200, sWb,104, 12,16,12, wm,wn,gid,tig);
    EPI(g_v, bv, 2);
    #undef ZACC
    #undef EPI
}

// ---------------- kernel 2: linear attention (unchanged) -----------------
__global__ __launch_bounds__(128) void k_attn()
{
    __shared__ __align__(16) float pool[4224*2 + 256];
    float* pK    = pool;
    float* pV    = pool + 4224;
    float* sKsum = pool + 8448;
    float* sZ    = pool + 8448 + 128;
    const int n = blockIdx.x;
    const int tid = threadIdx.x;

    for (int s = 0; s < 32; s++) {
        pK[s*132 + tid] = g_k[(size_t)(s*N_ + n)*C_ + tid];
        pV[s*132 + tid] = g_v[(size_t)(s*N_ + n)*C_ + tid];
    }
    __syncthreads();

    const int h = tid >> 5, d = tid & 31;
    float kv[32];
    #pragma unroll
    for (int vv = 0; vv < 32; vv++) kv[vv] = 0.f;
    float ks = 0.f;
    for (int s = 0; s < 32; s++) {
        float kd = pK[s*132 + h*32 + d];
        ks += kd;
        const float* vrow = &pV[s*132 + h*32];
        #pragma unroll
        for (int vv = 0; vv < 32; vv += 4) {
            float4 vf = *(const float4*)&vrow[vv];
            kv[vv+0] += kd * vf.x;
            kv[vv+1] += kd * vf.y;
            kv[vv+2] += kd * vf.z;
            kv[vv+3] += kd * vf.w;
        }
    }
    __syncthreads();
    #pragma unroll
    for (int vv = 0; vv < 32; vv++)
        pV[h*1056 + d*33 + vv] = kv[vv];
    sKsum[tid] = ks;
    for (int s = 0; s < 32; s++)
        pK[s*132 + tid] = g_q[(size_t)(s*N_ + n)*C_ + tid];
    __syncthreads();
    {
        int tz = tid >> 2, hz = tid & 3;
        float z = 0.f;
        #pragma unroll
        for (int dd = 0; dd < 32; dd++)
            z += pK[tz*132 + hz*32 + dd] * sKsum[hz*32 + dd];
        sZ[tz*4 + hz] = (float)T_ / (z + 1e-6f);
    }
    __syncthreads();
    const float* kvb = &pV[h*1056];
    for (int tt = 0; tt < 32; tt++) {
        float acc = 0.f;
        const float* qrow = &pK[tt*132 + h*32];
        #pragma unroll
        for (int dd = 0; dd < 32; dd++)
            acc += qrow[dd] * kvb[dd*33 + d];
        g_at[(size_t)(tt*N_ + n)*C_ + tid] = acc * sZ[tt*4 + h];
    }
}

// ---------------- kernel 3: FFN, pipelined cp.async + mma.sync -----------
// 512 thr, 16 warps (8m x 2n), CTA tile 128 rows.
// smem floats: sOH[128*136] | sU[128*136] | sWa[128*72] | sWb[128*72] | sM2 | sR2
__global__ __launch_bounds__(512) void k_ffn_tc(
    const float* __restrict__ x,
    const float* __restrict__ l1g, const float* __restrict__ l1b,
    const float* __restrict__ l2g, const float* __restrict__ l2b,
    const float* __restrict__ W1,  const float* __restrict__ b1f,
    const float* __restrict__ W2,  const float* __restrict__ b2f,
    float* __restrict__ out)
{
    extern __shared__ float sm[];
    float* sOH = sm;
    float* sU  = sm + 17408;
    float* sWa = sm + 34816;
    float* sWb = sm + 44032;
    float* sM2 = sm + 53248;
    float* sR2 = sm + 53376;
    const uint32_t sWau = (uint32_t)__cvta_generic_to_shared(sWa);
    const uint32_t sWbu = (uint32_t)__cvta_generic_to_shared(sWb);

    const int tid = threadIdx.x;
    const int lane = tid & 31, wid = tid >> 5;
    const int wm = wid >> 1, wn = wid & 1;
    const int gid = lane >> 2, tig = lane & 3;

    const int r0 = blockIdx.x * 128;
    const int t  = r0 / N_,  n0 = r0 % N_;
    const int b  = n0 / HW_, hw0 = n0 % HW_;

    // pre-issue W1(jc=0) halves so they land during the prologue
    fill_w(sWau, 72, W1, F_, 0,  64, 0, tid); CPCOMMIT();   // G0
    fill_w(sWbu, 72, W1, F_, 64, 64, 0, tid); CPCOMMIT();   // G1

    // ---- prologue: sOH = attn + ln1(x) (pad 136) ----
    {
        const int cc = (tid & 31) * 4;
        const int rb = tid >> 5;               // 0..15
        for (int j = 0; j < 8; j++) {
            int row = rb + 16*j;
            float4 a = *(const float4*)&g_at[(size_t)(r0+row)*C_ + cc];
            *(float4*)&sOH[row*136 + cc] = a;
        }
    }
    __syncthreads();
    {
        const int rl = tid & 127, cq = tid >> 7;
        const float mu = g_mu[r0+rl], rs = g_rs[r0+rl];
        const float* xb = x + (size_t)(b*T_+t)*C_*HW_ + hw0 + rl;
        for (int c = cq; c < C_; c += 4)
            sOH[rl*136 + c] += (xb[(size_t)c*HW_] - mu)*rs*l1g[c] + l1b[c];
    }
    __syncthreads();
    if (tid < 128) {   // ln2 stats
        float s = 0.f, s2 = 0.f;
        for (int c = 0; c < C_; c++) { float v = sOH[tid*136+c]; s += v; s2 += v*v; }
        float mu = s*(1.f/C_);
        sM2[tid] = mu;
        sR2[tid] = rsqrtf(s2*(1.f/C_) - mu*mu + 1e-5f);
    }
    __syncthreads();
    {   // sU = tf32(ln2(O)), interleaved, float2 stores
        const int rl = tid >> 2, sub = tid & 3;
        const float mu = sM2[rl], rs = sR2[rl];
        for (int q = sub; q < 16; q += 4)
            #pragma unroll
            for (int kb = 0; kb < 4; kb++){
                int c = q*8 + kb;
                float f0 = (sOH[rl*136 + c  ] - mu)*rs*l2g[c  ] + l2b[c  ];
                float f4 = (sOH[rl*136 + c+4] - mu)*rs*l2g[c+4] + l2b[c+4];
                *(float2*)&sU[rl*136 + q*8 + kb*2] = make_float2(rna(f0), rna(f4));
            }
    }
    // acc2 = O + b2 (residual + final bias pre-loaded; reads sOH before gelu reuse)
    float acc2[8][4];
    {
        const int ra = wm*16 + gid;
        #pragma unroll
        for (int j = 0; j < 8; j++){
            const int col = wn*64 + j*8 + 2*tig;
            acc2[j][0] = sOH[ra*136 + col]       + b2f[col];
            acc2[j][1] = sOH[ra*136 + col + 1]   + b2f[col+1];
            acc2[j][2] = sOH[(ra+8)*136 + col]   + b2f[col];
            acc2[j][3] = sOH[(ra+8)*136 + col+1] + b2f[col+1];
        }
    }
    __syncthreads();   // sU ready; all acc2-init reads of sOH done

    float acc1[8][4];
    for (int jc = 0; jc < 4; jc++) {
        CPWAIT(1); __syncthreads();            // W1 lo ready
        #pragma unroll
        for (int j = 0; j < 8; j++){
            const int col = jc*128 + wn*64 + j*8 + 2*tig;
            acc1[j][0] = b1f[col];   acc1[j][1] = b1f[col+1];
            acc1[j][2] = b1f[col];   acc1[j][3] = b1f[col+1];
        }
        mma_blk(acc1, sU,136, sWa,72, 0,8,0, wm,wn,gid,tig);
        __syncthreads(); fill_w(sWau, 72, W2, C_, jc*128,     64, 0, tid); CPCOMMIT();
        CPWAIT(1); __syncthreads();            // W1 hi ready
        mma_blk(acc1, sU,136, sWb,72, 8,16,8, wm,wn,gid,tig);
        // gelu -> sOH (interleaved layout for GEMM2 A-operand)
        {
            const int ra = wm*16 + gid;
            #pragma unroll
            for (int j = 0; j < 8; j++){
                const int c0 = wn*64 + j*8 + 2*tig, c1 = c0 + 1;
                float g0 = acc1[j][0], g1 = acc1[j][1];
                float g2 = acc1[j][2], g3 = acc1[j][3];
                g0 = rna(0.5f*g0*(1.f + erff(g0*0.70710678118f)));
                g1 = rna(0.5f*g1*(1.f + erff(g1*0.70710678118f)));
                g2 = rna(0.5f*g2*(1.f + erff(g2*0.70710678118f)));
                g3 = rna(0.5f*g3*(1.f + erff(g3*0.70710678118f)));
                sOH[ra*136     + kperm(c0)] = g0;
                sOH[ra*136     + kperm(c1)] = g1;
                sOH[(ra+8)*136 + kperm(c0)] = g2;
                sOH[(ra+8)*136 + kperm(c1)] = g3;
            }
        }
        __syncthreads(); fill_w(sWbu, 72, W2, C_, jc*128+64,  64, 0, tid); CPCOMMIT();
        CPWAIT(1); __syncthreads();            // W2 lo ready
        mma_blk(acc2, sOH,136, sWa,72, 0,8,0, wm,wn,gid,tig);
        __syncthreads();
        if (jc < 3){ fill_w(sWau, 72, W1, F_, 0,  64, (jc+1)*128, tid); CPCOMMIT(); }
        if (jc < 3){ CPWAIT(1); } else { CPWAIT(0); }
        __syncthreads();                       // W2 hi ready
        mma_blk(acc2, sOH,136, sWb,72, 8,16,8, wm,wn,gid,tig);
        __syncthreads();
        if (jc < 3){ fill_w(sWbu, 72, W1, F_, 64, 64, (jc+1)*128, tid); CPCOMMIT(); }
    }

    // ---- epilogue: direct transposed writeback ----
    {
        float* obase = out + (size_t)(b*T_+t)*C_*HW_ + hw0;
        const int ra = wm*16 + gid;
        #pragma unroll
        for (int j = 0; j < 8; j++){
            const int c0 = wn*64 + j*8 + 2*tig, c1 = c0 + 1;
            obase[(size_t)c0*HW_ + ra]     = acc2[j][0];
            obase[(size_t)c1*HW_ + ra]     = acc2[j][1];
            obase[(size_t)c0*HW_ + ra + 8] = acc2[j][2];
            obase[(size_t)c1*HW_ + ra + 8] = acc2[j][3];
        }
    }
}

// ---------------- launch --------------------------------------------------
extern "C" void kernel_launch(void* const* d_in, const int* in_sizes, int n_in,
                              void* d_out, int out_size)
{
    (void)in_sizes; (void)n_in; (void)out_size;
    const float* x   = (const float*)d_in[0];
    const float* gd  = (const float*)d_in[1];
    const float* Wq  = (const float*)d_in[2];
    const float* bq  = (const float*)d_in[3];
    const float* Wk  = (const float*)d_in[4];
    const float* bk  = (const float*)d_in[5];
    const float* Wv  = (const float*)d_in[6];
    const float* bv  = (const float*)d_in[7];
    const float* l1g = (const float*)d_in[8];
    const float* l1b = (const float*)d_in[9];
    const float* l2g = (const float*)d_in[10];
    const float* l2b = (const float*)d_in[11];
    const float* W1  = (const float*)d_in[12];
    const float* b1  = (const float*)d_in[13];
    const float* W2  = (const float*)d_in[14];
    const float* b2  = (const float*)d_in[15];
    float* out = (float*)d_out;

    const int smemQkv = (25600 + 2*13312) * 4;            // 208,896 B
    const int smemFfn = (17408*2 + 9216*2 + 256) * 4;     // 214,016 B
    cudaFuncSetAttribute(k_qkv_tc, cudaFuncAttributeMaxDynamicSharedMemorySize, smemQkv);
    cudaFuncSetAttribute(k_ffn_tc, cudaFuncAttributeMaxDynamicSharedMemorySize, smemFfn);

    k_qkv_tc<<<M_/128, 512, smemQkv>>>(x, gd, Wq, bq, Wk, bk, Wv, bv);
    k_attn  <<<N_, 128>>>();
    k_ffn_tc<<<M_/128, 512, smemFfn>>>(x, l1g, l1b, l2g, l2b, W1, b1, W2, b2, out);
}